// round 15
// baseline (speedup 1.0000x reference)
#include <cuda_runtime.h>
#include <mma.h>
#include <math.h>

using namespace nvcuda;

#define MAXM 400000

__device__ __align__(256) float g_taf[(size_t)MAXM * 56 + 4096];   // [M][56] tf32, col51=1, 52..55=0
__device__ __align__(256) float g_tafm[(size_t)MAXM * 48 + 4096];  // [M][48] tf32
__device__ float g_pf[MAXM + 1024];
__device__ float g_mf[MAXM + 1024];

__device__ __forceinline__ float sigmoidf_(float x) { return 1.f / (1.f + expf(-x)); }
__device__ __forceinline__ float tf32r(float x) { return wmma::__float_to_tf32(x); }

// ================= builder: 4 threads per point, 12 KNN dims each =================
__global__ __launch_bounds__(256, 4)
void build_kernel(const float* __restrict__ cam,
                  const float* __restrict__ anchors,
                  const float* __restrict__ scales,
                  const float* __restrict__ afeat,
                  const float* __restrict__ tfeat,
                  const float* __restrict__ factors,
                  const int* __restrict__ vis,
                  const int* __restrict__ knn,
                  float* __restrict__ out, int M)
{
    const int tid = threadIdx.x;
    const int m = blockIdx.x * 64 + (tid >> 2);
    const int h = tid & 3;
    if (m >= M) return;
    const int idx = vis[m];

    float4 fc = __ldg(reinterpret_cast<const float4*>(factors + (long long)idx * 4));
    const float tff = fc.x, mf = fc.y, kf = fc.z, pf = fc.w;

    float facc[12];
    #pragma unroll
    for (int i = 0; i < 12; i++) facc[i] = 0.f;

    const int* kp = knn + (long long)idx * 6;
    #pragma unroll 3
    for (int nb = 0; nb < 6; nb++) {
        int nidx = __ldg(kp + nb);
        float4 v[3];
        if (h == 0) {
            const float4* fa = reinterpret_cast<const float4*>(afeat + (long long)nidx * 32);
            v[0] = __ldg(fa + 0); v[1] = __ldg(fa + 1); v[2] = __ldg(fa + 2);
        } else if (h == 1) {
            const float4* fa = reinterpret_cast<const float4*>(afeat + (long long)nidx * 32 + 12);
            v[0] = __ldg(fa + 0); v[1] = __ldg(fa + 1); v[2] = __ldg(fa + 2);
        } else if (h == 2) {
            const float4* fa = reinterpret_cast<const float4*>(afeat + (long long)nidx * 32 + 24);
            v[0] = __ldg(fa + 0); v[1] = __ldg(fa + 1);
            v[2] = __ldg(reinterpret_cast<const float4*>(tfeat + (long long)nidx * 256 + 112));
        } else {
            const float4* ta = reinterpret_cast<const float4*>(tfeat + (long long)nidx * 256 + 116);
            v[0] = __ldg(ta + 0); v[1] = __ldg(ta + 1); v[2] = __ldg(ta + 2);
        }
        #pragma unroll
        for (int q = 0; q < 3; q++) {
            facc[4*q+0] += v[q].x; facc[4*q+1] += v[q].y;
            facc[4*q+2] += v[q].z; facc[4*q+3] += v[q].w;
        }
    }

    const float wk = (1.f - kf) * (1.f / 6.f);
    float4* tr = reinterpret_cast<float4*>(g_taf + (size_t)m * 56);
    float4* mr = reinterpret_cast<float4*>(g_tafm + (size_t)m * 48);

    if (h == 0) {
        float4 ov[3];
        const float4* fp = reinterpret_cast<const float4*>(afeat + (long long)idx * 32);
        ov[0] = __ldg(fp + 0); ov[1] = __ldg(fp + 1); ov[2] = __ldg(fp + 2);
        #pragma unroll
        for (int q = 0; q < 3; q++) {
            tr[q] = make_float4(tf32r(ov[q].x), tf32r(ov[q].y), tf32r(ov[q].z), tf32r(ov[q].w));
            mr[q] = make_float4(tf32r(fmaf(kf, ov[q].x, wk * facc[4*q+0])),
                                tf32r(fmaf(kf, ov[q].y, wk * facc[4*q+1])),
                                tf32r(fmaf(kf, ov[q].z, wk * facc[4*q+2])),
                                tf32r(fmaf(kf, ov[q].w, wk * facc[4*q+3])));
        }
        g_pf[m] = pf;
        g_mf[m] = mf;
        float ax = __ldg(anchors + (long long)idx * 3 + 0);
        float ay = __ldg(anchors + (long long)idx * 3 + 1);
        float az = __ldg(anchors + (long long)idx * 3 + 2);
        float* om = out + (long long)M * 110 + (long long)m * 50;
        const float* sp = scales + (long long)idx * 6;
        om[37] = expf(__ldg(sp + 0));
        om[38] = expf(__ldg(sp + 1));
        om[39] = expf(__ldg(sp + 2));
        om[40] = expf(__ldg(sp + 3)) * pf;
        om[41] = expf(__ldg(sp + 4)) * pf;
        om[42] = expf(__ldg(sp + 5)) * pf;
        om[43] = tff; om[44] = mf; om[45] = kf; om[46] = pf;
        om[47] = ax; om[48] = ay; om[49] = az;
    } else if (h == 1) {
        float4 ov[3];
        const float4* fp = reinterpret_cast<const float4*>(afeat + (long long)idx * 32 + 12);
        ov[0] = __ldg(fp + 0); ov[1] = __ldg(fp + 1); ov[2] = __ldg(fp + 2);
        #pragma unroll
        for (int q = 0; q < 3; q++) {
            tr[3 + q] = make_float4(tf32r(ov[q].x), tf32r(ov[q].y), tf32r(ov[q].z), tf32r(ov[q].w));
            mr[3 + q] = make_float4(tf32r(fmaf(kf, ov[q].x, wk * facc[4*q+0])),
                                    tf32r(fmaf(kf, ov[q].y, wk * facc[4*q+1])),
                                    tf32r(fmaf(kf, ov[q].z, wk * facc[4*q+2])),
                                    tf32r(fmaf(kf, ov[q].w, wk * facc[4*q+3])));
        }
    } else if (h == 2) {
        float4 of0, of1, t0, t1;
        {
            const float4* fp = reinterpret_cast<const float4*>(afeat + (long long)idx * 32 + 24);
            of0 = __ldg(fp + 0); of1 = __ldg(fp + 1);
            const float4* tp = reinterpret_cast<const float4*>(tfeat + (long long)idx * 256 + 112);
            t0 = __ldg(tp + 0); t1 = __ldg(tp + 1);
        }
        float ax = __ldg(anchors + (long long)idx * 3 + 0);
        float ay = __ldg(anchors + (long long)idx * 3 + 1);
        float az = __ldg(anchors + (long long)idx * 3 + 2);
        float vx = ax - cam[3], vy = ay - cam[7], vz = az - cam[11];
        float nrm = sqrtf(vx*vx + vy*vy + vz*vz);
        float inv = 1.f / fmaxf(nrm, 1e-8f);

        float ts0 = t0.x * tff, ts1 = t0.y * tff, ts2 = t0.z * tff, ts3 = t0.w * tff;
        float ts4 = t1.x * tff;

        tr[6] = make_float4(tf32r(of0.x), tf32r(of0.y), tf32r(of0.z), tf32r(of0.w));
        tr[7] = make_float4(tf32r(of1.x), tf32r(of1.y), tf32r(of1.z), tf32r(of1.w));
        tr[8] = make_float4(tf32r(vx*inv), tf32r(vy*inv), tf32r(vz*inv), tf32r(ts0));
        tr[9] = make_float4(tf32r(ts1), tf32r(ts2), tf32r(ts3), tf32r(ts4));

        mr[6] = make_float4(tf32r(fmaf(kf, of0.x, wk*facc[0])), tf32r(fmaf(kf, of0.y, wk*facc[1])),
                            tf32r(fmaf(kf, of0.z, wk*facc[2])), tf32r(fmaf(kf, of0.w, wk*facc[3])));
        mr[7] = make_float4(tf32r(fmaf(kf, of1.x, wk*facc[4])), tf32r(fmaf(kf, of1.y, wk*facc[5])),
                            tf32r(fmaf(kf, of1.z, wk*facc[6])), tf32r(fmaf(kf, of1.w, wk*facc[7])));
        mr[8] = make_float4(tf32r(fmaf(kf, ts0, wk*facc[8])),  tf32r(fmaf(kf, ts1, wk*facc[9])),
                            tf32r(fmaf(kf, ts2, wk*facc[10])), tf32r(fmaf(kf, ts3, wk*facc[11])));
    } else {
        float4 t1, t2, t3;
        {
            const float4* tp = reinterpret_cast<const float4*>(tfeat + (long long)idx * 256 + 116);
            t1 = __ldg(tp + 0); t2 = __ldg(tp + 1); t3 = __ldg(tp + 2);
        }
        float ts[12];
        ts[0] = t1.x*tff; ts[1] = t1.y*tff; ts[2] = t1.z*tff; ts[3] = t1.w*tff;
        ts[4] = t2.x*tff; ts[5] = t2.y*tff; ts[6] = t2.z*tff; ts[7] = t2.w*tff;
        ts[8] = t3.x*tff; ts[9] = t3.y*tff; ts[10] = t3.z*tff; ts[11] = t3.w*tff;

        tr[10] = make_float4(tf32r(ts[1]), tf32r(ts[2]), tf32r(ts[3]), tf32r(ts[4]));
        tr[11] = make_float4(tf32r(ts[5]), tf32r(ts[6]), tf32r(ts[7]), tf32r(ts[8]));
        tr[12] = make_float4(tf32r(ts[9]), tf32r(ts[10]), tf32r(ts[11]), 1.0f);   // col 51 = 1 (bias row)
        tr[13] = make_float4(0.f, 0.f, 0.f, 0.f);

        mr[9]  = make_float4(tf32r(fmaf(kf, ts[0], wk*facc[0])), tf32r(fmaf(kf, ts[1], wk*facc[1])),
                             tf32r(fmaf(kf, ts[2], wk*facc[2])), tf32r(fmaf(kf, ts[3], wk*facc[3])));
        mr[10] = make_float4(tf32r(fmaf(kf, ts[4], wk*facc[4])), tf32r(fmaf(kf, ts[5], wk*facc[5])),
                             tf32r(fmaf(kf, ts[6], wk*facc[6])), tf32r(fmaf(kf, ts[7], wk*facc[7])));
        mr[11] = make_float4(tf32r(fmaf(kf, ts[8], wk*facc[8])), tf32r(fmaf(kf, ts[9], wk*facc[9])),
                             tf32r(fmaf(kf, ts[10], wk*facc[10])), tf32r(fmaf(kf, ts[11], wk*facc[11])));
    }
}

// ================= mlp3: bias-in-row-51, 14 warps, 2 M-tiles/warp, A-frags in regs =================
#define W1S 192
#define W2S 128
#define HS3 84
#define OW1_3 0
#define OW2_3 10752
#define OB2_3  18944          // 128 raw b2 (epilogue)
#define OWRP_3 19072
#define SLAB_3 2688           // 32*84
#define NW3 14
#define NT3 (NW3 * 32)
#define SMEM3_FLOATS (OWRP_3 + NW3 * SLAB_3)   // 56704 floats = 226,816 B

__global__ __launch_bounds__(NT3, 1)
void mlp3_kernel(const float* __restrict__ xin,
                 const float* __restrict__ op_w1,  const float* __restrict__ op_b1,
                 const float* __restrict__ op_w2,  const float* __restrict__ op_b2,
                 const float* __restrict__ col_w1, const float* __restrict__ col_b1,
                 const float* __restrict__ col_w2, const float* __restrict__ col_b2,
                 const float* __restrict__ cov_w1, const float* __restrict__ cov_b1,
                 const float* __restrict__ cov_w2, const float* __restrict__ cov_b2,
                 const float* __restrict__ pfv,
                 float* __restrict__ out, int M)
{
    extern __shared__ float S[];
    const int tid = threadIdx.x;
    const int warp = tid >> 5;
    const int lane = tid & 31;

    // W1c: rows 0..50 = weights, row 51 = bias, rows 52..55 = 0
    for (int i = tid; i < 56 * W1S; i += NT3) {
        int row = i / W1S, c = i - row * W1S;
        int sel = c >> 6, cc = c & 63;
        float v = 0.f;
        if (row < 51)
            v = (sel == 0) ? op_w1[row * 64 + cc]
              : (sel == 1) ? col_w1[row * 64 + cc]
                           : cov_w1[row * 64 + cc];
        else if (row == 51)
            v = (sel == 0) ? op_b1[cc] : (sel == 1) ? col_b1[cc] : cov_b1[cc];
        S[OW1_3 + i] = tf32r(v);
    }
    for (int i = tid; i < 64 * W2S; i += NT3) {
        int j = i >> 7, c = i & 127;
        float v = 0.f;
        if (c < 16)       { if (c < 10)      v = op_w2 [j * 10 + c]; }
        else if (c < 48)  { if (c - 16 < 30) v = col_w2[j * 30 + (c - 16)]; }
        else              { if (c - 48 < 70) v = cov_w2[j * 70 + (c - 48)]; }
        S[OW2_3 + i] = tf32r(v);
    }
    if (tid < W2S) {
        float v = 0.f;
        if (tid < 16)      { if (tid < 10)      v = op_b2 [tid]; }
        else if (tid < 48) { if (tid - 16 < 30) v = col_b2[tid - 16]; }
        else               { if (tid - 48 < 70) v = cov_b2[tid - 48]; }
        S[OB2_3 + tid] = v;
    }
    __syncthreads();

    float* Xp = S + OWRP_3 + warp * SLAB_3;
    const int tiles32 = (M + 31) >> 5;

    for (int t = blockIdx.x * NW3 + warp; t < tiles32; t += gridDim.x * NW3) {
        {
            const float* src = xin + (size_t)t * 32 * 56;
            #pragma unroll
            for (int it = 0; it < 14; it++) {
                int e = lane * 4 + it * 128;
                float4 v = __ldg(reinterpret_cast<const float4*>(src + e));
                int row = e / 56, c = e - row * 56;
                *reinterpret_cast<float4*>(Xp + row * HS3 + c) = v;
            }
        }
        __syncwarp();

        wmma::fragment<wmma::matrix_a, 16, 16, 8, wmma::precision::tf32, wmma::row_major> af[2][7];
        #pragma unroll
        for (int k = 0; k < 7; k++) {
            wmma::load_matrix_sync(af[0][k], Xp + k * 8, HS3);
            wmma::load_matrix_sync(af[1][k], Xp + 16 * HS3 + k * 8, HS3);
        }
        __syncwarp();

        size_t mlane = (size_t)t * 32 + lane;
        bool valid = (mlane < (size_t)M);
        float pf = valid ? __ldg(pfv + mlane) : 0.f;
        float* omk = out + mlane * 110;
        const float* cr = Xp + lane * HS3;

        #pragma unroll 1
        for (int s = 0; s < 3; s++) {
            wmma::fragment<wmma::accumulator, 16, 16, 8, float> c1[2][4];
            #pragma unroll
            for (int n = 0; n < 4; n++) {
                wmma::fill_fragment(c1[0][n], 0.f);
                wmma::fill_fragment(c1[1][n], 0.f);
            }
            #pragma unroll
            for (int k = 0; k < 7; k++) {
                #pragma unroll
                for (int n = 0; n < 4; n++) {
                    wmma::fragment<wmma::matrix_b, 16, 16, 8, wmma::precision::tf32, wmma::row_major> bf;
                    wmma::load_matrix_sync(bf, S + OW1_3 + (k * 8) * W1S + s * 64 + n * 16, W1S);
                    wmma::mma_sync(c1[0][n], af[0][k], bf, c1[0][n]);
                    wmma::mma_sync(c1[1][n], af[1][k], bf, c1[1][n]);
                }
            }
            #pragma unroll
            for (int tt = 0; tt < 2; tt++)
                #pragma unroll
                for (int n = 0; n < 4; n++) {
                    #pragma unroll
                    for (int i = 0; i < c1[tt][n].num_elements; i++)
                        c1[tt][n].x[i] = tf32r(fmaxf(c1[tt][n].x[i], 0.f));
                    wmma::store_matrix_sync(Xp + tt * 16 * HS3 + n * 16, c1[tt][n], HS3, wmma::mem_row_major);
                }
            __syncwarp();

            if (s == 0) {
                wmma::fragment<wmma::accumulator, 16, 16, 8, float> c2[2];
                #pragma unroll
                for (int tt = 0; tt < 2; tt++) wmma::fill_fragment(c2[tt], 0.f);
                #pragma unroll 1
                for (int k = 0; k < 8; k++) {
                    wmma::fragment<wmma::matrix_a, 16, 16, 8, wmma::precision::tf32, wmma::row_major> a0, a1;
                    wmma::load_matrix_sync(a0, Xp + k * 8, HS3);
                    wmma::load_matrix_sync(a1, Xp + 16 * HS3 + k * 8, HS3);
                    wmma::fragment<wmma::matrix_b, 16, 16, 8, wmma::precision::tf32, wmma::row_major> bf;
                    wmma::load_matrix_sync(bf, S + OW2_3 + (k * 8) * W2S + 0, W2S);
                    wmma::mma_sync(c2[0], a0, bf, c2[0]);
                    wmma::mma_sync(c2[1], a1, bf, c2[1]);
                }
                __syncwarp();
                wmma::store_matrix_sync(Xp, c2[0], HS3, wmma::mem_row_major);
                wmma::store_matrix_sync(Xp + 16 * HS3, c2[1], HS3, wmma::mem_row_major);
                __syncwarp();
                if (valid) {
                    #pragma unroll
                    for (int k = 0; k < 10; k++)
                        omk[k * 11] = tanhf(cr[k] + S[OB2_3 + k]) * pf;
                }
            } else if (s == 1) {
                wmma::fragment<wmma::accumulator, 16, 16, 8, float> c2[2][2];
                #pragma unroll
                for (int tt = 0; tt < 2; tt++)
                    #pragma unroll
                    for (int n = 0; n < 2; n++) wmma::fill_fragment(c2[tt][n], 0.f);
                #pragma unroll 1
                for (int k = 0; k < 8; k++) {
                    wmma::fragment<wmma::matrix_a, 16, 16, 8, wmma::precision::tf32, wmma::row_major> a0, a1;
                    wmma::load_matrix_sync(a0, Xp + k * 8, HS3);
                    wmma::load_matrix_sync(a1, Xp + 16 * HS3 + k * 8, HS3);
                    #pragma unroll
                    for (int n = 0; n < 2; n++) {
                        wmma::fragment<wmma::matrix_b, 16, 16, 8, wmma::precision::tf32, wmma::row_major> bf;
                        wmma::load_matrix_sync(bf, S + OW2_3 + (k * 8) * W2S + 16 + n * 16, W2S);
                        wmma::mma_sync(c2[0][n], a0, bf, c2[0][n]);
                        wmma::mma_sync(c2[1][n], a1, bf, c2[1][n]);
                    }
                }
                __syncwarp();
                #pragma unroll
                for (int tt = 0; tt < 2; tt++)
                    #pragma unroll
                    for (int n = 0; n < 2; n++)
                        wmma::store_matrix_sync(Xp + tt * 16 * HS3 + n * 16, c2[tt][n], HS3, wmma::mem_row_major);
                __syncwarp();
                if (valid) {
                    #pragma unroll
                    for (int k = 0; k < 30; k++) {
                        int kd = k / 3;
                        omk[kd * 11 + 1 + (k - kd * 3)] = sigmoidf_(cr[k] + S[OB2_3 + 16 + k]);
                    }
                }
            } else {
                wmma::fragment<wmma::accumulator, 16, 16, 8, float> c2[2][5];
                #pragma unroll
                for (int tt = 0; tt < 2; tt++)
                    #pragma unroll
                    for (int n = 0; n < 5; n++) wmma::fill_fragment(c2[tt][n], 0.f);
                #pragma unroll 1
                for (int k = 0; k < 8; k++) {
                    wmma::fragment<wmma::matrix_a, 16, 16, 8, wmma::precision::tf32, wmma::row_major> a0, a1;
                    wmma::load_matrix_sync(a0, Xp + k * 8, HS3);
                    wmma::load_matrix_sync(a1, Xp + 16 * HS3 + k * 8, HS3);
                    #pragma unroll
                    for (int n = 0; n < 5; n++) {
                        wmma::fragment<wmma::matrix_b, 16, 16, 8, wmma::precision::tf32, wmma::row_major> bf;
                        wmma::load_matrix_sync(bf, S + OW2_3 + (k * 8) * W2S + 48 + n * 16, W2S);
                        wmma::mma_sync(c2[0][n], a0, bf, c2[0][n]);
                        wmma::mma_sync(c2[1][n], a1, bf, c2[1][n]);
                    }
                }
                __syncwarp();
                #pragma unroll
                for (int tt = 0; tt < 2; tt++)
                    #pragma unroll
                    for (int n = 0; n < 5; n++)
                        wmma::store_matrix_sync(Xp + tt * 16 * HS3 + n * 16, c2[tt][n], HS3, wmma::mem_row_major);
                __syncwarp();
                if (valid) {
                    #pragma unroll
                    for (int k = 0; k < 70; k++) {
                        int kd = k / 7;
                        omk[kd * 11 + 4 + (k - kd * 7)] = cr[k] + S[OB2_3 + 48 + k];
                    }
                }
            }
            __syncwarp();
        }
    }
}

// ================= motion: 32-pt tiles, 2 M-tiles/warp, float2 epilogue (R14, committed) =================
#define MHS2 68
#define OW1_M 0
#define OW2_M 3072
#define OB1R_M 6144
#define OB2R_M 7168
#define OWRP_M 7936
#define SLAB_M2 2176          // 32*68
#define SMEMM_FLOATS (OWRP_M + 8 * SLAB_M2)

__global__ __launch_bounds__(256, 2)
void mlp_mot_kernel(const float* __restrict__ xin,
                    const float* __restrict__ w1g, const float* __restrict__ b1g,
                    const float* __restrict__ w2g, const float* __restrict__ b2g,
                    const float* __restrict__ mfv,
                    float* __restrict__ out, int M)
{
    extern __shared__ float S[];
    const int tid = threadIdx.x;
    const int warp = tid >> 5;
    const int lane = tid & 31;

    for (int i = tid; i < 48 * 64; i += 256) S[OW1_M + i] = tf32r(w1g[i]);
    for (int i = tid; i < 64 * 48; i += 256) {
        int j = i / 48, k = i - j * 48;
        S[OW2_M + i] = (k < 37) ? tf32r(w2g[j * 37 + k]) : 0.f;
    }
    if (tid < 64) {
        float acc = b1g[tid];
        #pragma unroll
        for (int t = 0; t < 8; t++) {
            float ang = exp2f((float)t) * 1.5707963267948966f;
            acc = fmaf(sinf(ang), w1g[(48 + t) * 64 + tid], acc);
            acc = fmaf(cosf(ang), w1g[(56 + t) * 64 + tid], acc);
        }
        S[OB1R_M + tid] = acc;
    }
    if (tid < 48) S[OB2R_M + tid] = (tid < 37) ? b2g[tid] : 0.f;
    __syncthreads();
    for (int i = tid; i < 16 * 64; i += 256)
        if (i >= 64) S[OB1R_M + i] = S[OB1R_M + (i & 63)];
    for (int i = tid; i < 16 * 48; i += 256)
        if (i >= 48) S[OB2R_M + i] = S[OB2R_M + (i % 48)];
    __syncthreads();

    float* Xp = S + OWRP_M + warp * SLAB_M2;
    const int tiles32 = (M + 31) >> 5;

    for (int t = blockIdx.x * 8 + warp; t < tiles32; t += gridDim.x * 8) {
        {
            const float* src = xin + (size_t)t * 32 * 48;
            #pragma unroll
            for (int it = 0; it < 12; it++) {
                int e = lane * 4 + it * 128;
                float4 v = __ldg(reinterpret_cast<const float4*>(src + e));
                int row = e / 48, c = e - row * 48;
                *reinterpret_cast<float4*>(Xp + row * MHS2 + c) = v;
            }
        }
        __syncwarp();

        wmma::fragment<wmma::accumulator, 16, 16, 8, float> c1[2][4];
        #pragma unroll
        for (int n = 0; n < 4; n++) {
            wmma::load_matrix_sync(c1[0][n], S + OB1R_M + n * 16, 64, wmma::mem_row_major);
            wmma::load_matrix_sync(c1[1][n], S + OB1R_M + n * 16, 64, wmma::mem_row_major);
        }
        #pragma unroll 1
        for (int k = 0; k < 6; k++) {
            wmma::fragment<wmma::matrix_a, 16, 16, 8, wmma::precision::tf32, wmma::row_major> a0, a1;
            wmma::load_matrix_sync(a0, Xp + k * 8, MHS2);
            wmma::load_matrix_sync(a1, Xp + 16 * MHS2 + k * 8, MHS2);
            #pragma unroll
            for (int n = 0; n < 4; n++) {
                wmma::fragment<wmma::matrix_b, 16, 16, 8, wmma::precision::tf32, wmma::row_major> bf;
                wmma::load_matrix_sync(bf, S + OW1_M + k * 8 * 64 + n * 16, 64);
                wmma::mma_sync(c1[0][n], a0, bf, c1[0][n]);
                wmma::mma_sync(c1[1][n], a1, bf, c1[1][n]);
            }
        }
        #pragma unroll
        for (int tt = 0; tt < 2; tt++)
            #pragma unroll
            for (int n = 0; n < 4; n++) {
                #pragma unroll
                for (int i = 0; i < c1[tt][n].num_elements; i++)
                    c1[tt][n].x[i] = tf32r(fmaxf(c1[tt][n].x[i], 0.f));
                wmma::store_matrix_sync(Xp + tt * 16 * MHS2 + n * 16, c1[tt][n], MHS2, wmma::mem_row_major);
            }
        __syncwarp();

        wmma::fragment<wmma::accumulator, 16, 16, 8, float> c2[2][3];
        #pragma unroll
        for (int n = 0; n < 3; n++) {
            wmma::load_matrix_sync(c2[0][n], S + OB2R_M + n * 16, 48, wmma::mem_row_major);
            wmma::load_matrix_sync(c2[1][n], S + OB2R_M + n * 16, 48, wmma::mem_row_major);
        }
        #pragma unroll 1
        for (int k = 0; k < 8; k++) {
            wmma::fragment<wmma::matrix_a, 16, 16, 8, wmma::precision::tf32, wmma::row_major> a0, a1;
            wmma::load_matrix_sync(a0, Xp + k * 8, MHS2);
            wmma::load_matrix_sync(a1, Xp + 16 * MHS2 + k * 8, MHS2);
            #pragma unroll
            for (int n = 0; n < 3; n++) {
                wmma::fragment<wmma::matrix_b, 16, 16, 8, wmma::precision::tf32, wmma::row_major> bf;
                wmma::load_matrix_sync(bf, S + OW2_M + k * 8 * 48 + n * 16, 48);
                wmma::mma_sync(c2[0][n], a0, bf, c2[0][n]);
                wmma::mma_sync(c2[1][n], a1, bf, c2[1][n]);
            }
        }
        __syncwarp();
        #pragma unroll
        for (int tt = 0; tt < 2; tt++)
            #pragma unroll
            for (int n = 0; n < 3; n++)
                wmma::store_matrix_sync(Xp + tt * 16 * MHS2 + n * 16, c2[tt][n], MHS2, wmma::mem_row_major);
        __syncwarp();

        {
            size_t m = (size_t)t * 32 + lane;
            if (m < (size_t)M) {
                float mfs = __ldg(mfv + m);
                float* om = out + (size_t)M * 110 + m * 50;
                const float* r = Xp + lane * MHS2;
                #pragma unroll
                for (int q = 0; q < 18; q++) {
                    float2 v = make_float2(r[2*q] * mfs, r[2*q+1] * mfs);
                    *reinterpret_cast<float2*>(om + 2*q) = v;
                }
                om[36] = r[36] * mfs;
            }
        }
        __syncwarp();
    }
}

// ================= launch =================
extern "C" void kernel_launch(void* const* d_in, const int* in_sizes, int n_in,
                              void* d_out, int out_size)
{
    const float* cam     = (const float*)d_in[0];
    const float* anchors = (const float*)d_in[1];
    const float* scales  = (const float*)d_in[2];
    const float* afeat   = (const float*)d_in[3];
    const float* tfeat   = (const float*)d_in[4];
    const float* factors = (const float*)d_in[5];
    const float* op_w1   = (const float*)d_in[6];
    const float* op_b1   = (const float*)d_in[7];
    const float* op_w2   = (const float*)d_in[8];
    const float* op_b2   = (const float*)d_in[9];
    const float* col_w1  = (const float*)d_in[10];
    const float* col_b1  = (const float*)d_in[11];
    const float* col_w2  = (const float*)d_in[12];
    const float* col_b2  = (const float*)d_in[13];
    const float* cov_w1  = (const float*)d_in[14];
    const float* cov_b1  = (const float*)d_in[15];
    const float* cov_w2  = (const float*)d_in[16];
    const float* cov_b2  = (const float*)d_in[17];
    const float* mot_w1  = (const float*)d_in[18];
    const float* mot_b1  = (const float*)d_in[19];
    const float* mot_w2  = (const float*)d_in[20];
    const float* mot_b2  = (const float*)d_in[21];
    const int*   vis     = (const int*)d_in[22];
    const int*   knn     = (const int*)d_in[23];

    int M = in_sizes[22];
    float* out = (float*)d_out;

    float *taf, *tafm, *pf, *mf;
    cudaGetSymbolAddress((void**)&taf,  g_taf);
    cudaGetSymbolAddress((void**)&tafm, g_tafm);
    cudaGetSymbolAddress((void**)&pf,   g_pf);
    cudaGetSymbolAddress((void**)&mf,   g_mf);

    const int GB = (M + 63) / 64;

    const int SMEM3 = SMEM3_FLOATS * 4;   // 226,816 B
    const int SMEMM = SMEMM_FLOATS * 4;
    cudaFuncSetAttribute(mlp3_kernel,    cudaFuncAttributeMaxDynamicSharedMemorySize, SMEM3);
    cudaFuncSetAttribute(mlp_mot_kernel, cudaFuncAttributeMaxDynamicSharedMemorySize, SMEMM);

    build_kernel<<<GB, 256>>>(cam, anchors, scales, afeat, tfeat, factors, vis, knn, out, M);
    mlp3_kernel<<<148, NT3, SMEM3>>>(
        taf,
        op_w1, op_b1, op_w2, op_b2,
        col_w1, col_b1, col_w2, col_b2,
        cov_w1, cov_b1, cov_w2, cov_b2,
        pf, out, M);
    mlp_mot_kernel<<<296, 256, SMEMM>>>(tafm, mot_w1, mot_b1, mot_w2, mot_b2, mf, out, M);
}

// round 16
// speedup vs baseline: 1.1272x; 1.1272x over previous
#include <cuda_runtime.h>
#include <mma.h>
#include <math.h>

using namespace nvcuda;

#define MAXM 400000

__device__ __align__(256) float g_taf[(size_t)MAXM * 56 + 4096];   // [M][56] tf32, col51=1, 52..55=0
__device__ __align__(256) float g_tafm[(size_t)MAXM * 48 + 4096];  // [M][48] tf32
__device__ float g_pf[MAXM + 1024];
__device__ float g_mf[MAXM + 1024];

__device__ __forceinline__ float sigmoidf_(float x) { return 1.f / (1.f + expf(-x)); }
__device__ __forceinline__ float tf32r(float x) { return wmma::__float_to_tf32(x); }

// ================= builder: 4 threads per point, 12 KNN dims each (committed) =================
__global__ __launch_bounds__(256, 4)
void build_kernel(const float* __restrict__ cam,
                  const float* __restrict__ anchors,
                  const float* __restrict__ scales,
                  const float* __restrict__ afeat,
                  const float* __restrict__ tfeat,
                  const float* __restrict__ factors,
                  const int* __restrict__ vis,
                  const int* __restrict__ knn,
                  float* __restrict__ out, int M)
{
    const int tid = threadIdx.x;
    const int m = blockIdx.x * 64 + (tid >> 2);
    const int h = tid & 3;
    if (m >= M) return;
    const int idx = vis[m];

    float4 fc = __ldg(reinterpret_cast<const float4*>(factors + (long long)idx * 4));
    const float tff = fc.x, mf = fc.y, kf = fc.z, pf = fc.w;

    float facc[12];
    #pragma unroll
    for (int i = 0; i < 12; i++) facc[i] = 0.f;

    const int* kp = knn + (long long)idx * 6;
    #pragma unroll 3
    for (int nb = 0; nb < 6; nb++) {
        int nidx = __ldg(kp + nb);
        float4 v[3];
        if (h == 0) {
            const float4* fa = reinterpret_cast<const float4*>(afeat + (long long)nidx * 32);
            v[0] = __ldg(fa + 0); v[1] = __ldg(fa + 1); v[2] = __ldg(fa + 2);
        } else if (h == 1) {
            const float4* fa = reinterpret_cast<const float4*>(afeat + (long long)nidx * 32 + 12);
            v[0] = __ldg(fa + 0); v[1] = __ldg(fa + 1); v[2] = __ldg(fa + 2);
        } else if (h == 2) {
            const float4* fa = reinterpret_cast<const float4*>(afeat + (long long)nidx * 32 + 24);
            v[0] = __ldg(fa + 0); v[1] = __ldg(fa + 1);
            v[2] = __ldg(reinterpret_cast<const float4*>(tfeat + (long long)nidx * 256 + 112));
        } else {
            const float4* ta = reinterpret_cast<const float4*>(tfeat + (long long)nidx * 256 + 116);
            v[0] = __ldg(ta + 0); v[1] = __ldg(ta + 1); v[2] = __ldg(ta + 2);
        }
        #pragma unroll
        for (int q = 0; q < 3; q++) {
            facc[4*q+0] += v[q].x; facc[4*q+1] += v[q].y;
            facc[4*q+2] += v[q].z; facc[4*q+3] += v[q].w;
        }
    }

    const float wk = (1.f - kf) * (1.f / 6.f);
    float4* tr = reinterpret_cast<float4*>(g_taf + (size_t)m * 56);
    float4* mr = reinterpret_cast<float4*>(g_tafm + (size_t)m * 48);

    if (h == 0) {
        float4 ov[3];
        const float4* fp = reinterpret_cast<const float4*>(afeat + (long long)idx * 32);
        ov[0] = __ldg(fp + 0); ov[1] = __ldg(fp + 1); ov[2] = __ldg(fp + 2);
        #pragma unroll
        for (int q = 0; q < 3; q++) {
            tr[q] = make_float4(tf32r(ov[q].x), tf32r(ov[q].y), tf32r(ov[q].z), tf32r(ov[q].w));
            mr[q] = make_float4(tf32r(fmaf(kf, ov[q].x, wk * facc[4*q+0])),
                                tf32r(fmaf(kf, ov[q].y, wk * facc[4*q+1])),
                                tf32r(fmaf(kf, ov[q].z, wk * facc[4*q+2])),
                                tf32r(fmaf(kf, ov[q].w, wk * facc[4*q+3])));
        }
        g_pf[m] = pf;
        g_mf[m] = mf;
        float ax = __ldg(anchors + (long long)idx * 3 + 0);
        float ay = __ldg(anchors + (long long)idx * 3 + 1);
        float az = __ldg(anchors + (long long)idx * 3 + 2);
        float* om = out + (long long)M * 110 + (long long)m * 50;
        const float* sp = scales + (long long)idx * 6;
        om[37] = expf(__ldg(sp + 0));
        om[38] = expf(__ldg(sp + 1));
        om[39] = expf(__ldg(sp + 2));
        om[40] = expf(__ldg(sp + 3)) * pf;
        om[41] = expf(__ldg(sp + 4)) * pf;
        om[42] = expf(__ldg(sp + 5)) * pf;
        om[43] = tff; om[44] = mf; om[45] = kf; om[46] = pf;
        om[47] = ax; om[48] = ay; om[49] = az;
    } else if (h == 1) {
        float4 ov[3];
        const float4* fp = reinterpret_cast<const float4*>(afeat + (long long)idx * 32 + 12);
        ov[0] = __ldg(fp + 0); ov[1] = __ldg(fp + 1); ov[2] = __ldg(fp + 2);
        #pragma unroll
        for (int q = 0; q < 3; q++) {
            tr[3 + q] = make_float4(tf32r(ov[q].x), tf32r(ov[q].y), tf32r(ov[q].z), tf32r(ov[q].w));
            mr[3 + q] = make_float4(tf32r(fmaf(kf, ov[q].x, wk * facc[4*q+0])),
                                    tf32r(fmaf(kf, ov[q].y, wk * facc[4*q+1])),
                                    tf32r(fmaf(kf, ov[q].z, wk * facc[4*q+2])),
                                    tf32r(fmaf(kf, ov[q].w, wk * facc[4*q+3])));
        }
    } else if (h == 2) {
        float4 of0, of1, t0, t1;
        {
            const float4* fp = reinterpret_cast<const float4*>(afeat + (long long)idx * 32 + 24);
            of0 = __ldg(fp + 0); of1 = __ldg(fp + 1);
            const float4* tp = reinterpret_cast<const float4*>(tfeat + (long long)idx * 256 + 112);
            t0 = __ldg(tp + 0); t1 = __ldg(tp + 1);
        }
        float ax = __ldg(anchors + (long long)idx * 3 + 0);
        float ay = __ldg(anchors + (long long)idx * 3 + 1);
        float az = __ldg(anchors + (long long)idx * 3 + 2);
        float vx = ax - cam[3], vy = ay - cam[7], vz = az - cam[11];
        float nrm = sqrtf(vx*vx + vy*vy + vz*vz);
        float inv = 1.f / fmaxf(nrm, 1e-8f);

        float ts0 = t0.x * tff, ts1 = t0.y * tff, ts2 = t0.z * tff, ts3 = t0.w * tff;
        float ts4 = t1.x * tff;

        tr[6] = make_float4(tf32r(of0.x), tf32r(of0.y), tf32r(of0.z), tf32r(of0.w));
        tr[7] = make_float4(tf32r(of1.x), tf32r(of1.y), tf32r(of1.z), tf32r(of1.w));
        tr[8] = make_float4(tf32r(vx*inv), tf32r(vy*inv), tf32r(vz*inv), tf32r(ts0));
        tr[9] = make_float4(tf32r(ts1), tf32r(ts2), tf32r(ts3), tf32r(ts4));

        mr[6] = make_float4(tf32r(fmaf(kf, of0.x, wk*facc[0])), tf32r(fmaf(kf, of0.y, wk*facc[1])),
                            tf32r(fmaf(kf, of0.z, wk*facc[2])), tf32r(fmaf(kf, of0.w, wk*facc[3])));
        mr[7] = make_float4(tf32r(fmaf(kf, of1.x, wk*facc[4])), tf32r(fmaf(kf, of1.y, wk*facc[5])),
                            tf32r(fmaf(kf, of1.z, wk*facc[6])), tf32r(fmaf(kf, of1.w, wk*facc[7])));
        mr[8] = make_float4(tf32r(fmaf(kf, ts0, wk*facc[8])),  tf32r(fmaf(kf, ts1, wk*facc[9])),
                            tf32r(fmaf(kf, ts2, wk*facc[10])), tf32r(fmaf(kf, ts3, wk*facc[11])));
    } else {
        float4 t1, t2, t3;
        {
            const float4* tp = reinterpret_cast<const float4*>(tfeat + (long long)idx * 256 + 116);
            t1 = __ldg(tp + 0); t2 = __ldg(tp + 1); t3 = __ldg(tp + 2);
        }
        float ts[12];
        ts[0] = t1.x*tff; ts[1] = t1.y*tff; ts[2] = t1.z*tff; ts[3] = t1.w*tff;
        ts[4] = t2.x*tff; ts[5] = t2.y*tff; ts[6] = t2.z*tff; ts[7] = t2.w*tff;
        ts[8] = t3.x*tff; ts[9] = t3.y*tff; ts[10] = t3.z*tff; ts[11] = t3.w*tff;

        tr[10] = make_float4(tf32r(ts[1]), tf32r(ts[2]), tf32r(ts[3]), tf32r(ts[4]));
        tr[11] = make_float4(tf32r(ts[5]), tf32r(ts[6]), tf32r(ts[7]), tf32r(ts[8]));
        tr[12] = make_float4(tf32r(ts[9]), tf32r(ts[10]), tf32r(ts[11]), 1.0f);   // col 51 = 1 (bias row)
        tr[13] = make_float4(0.f, 0.f, 0.f, 0.f);

        mr[9]  = make_float4(tf32r(fmaf(kf, ts[0], wk*facc[0])), tf32r(fmaf(kf, ts[1], wk*facc[1])),
                             tf32r(fmaf(kf, ts[2], wk*facc[2])), tf32r(fmaf(kf, ts[3], wk*facc[3])));
        mr[10] = make_float4(tf32r(fmaf(kf, ts[4], wk*facc[4])), tf32r(fmaf(kf, ts[5], wk*facc[5])),
                             tf32r(fmaf(kf, ts[6], wk*facc[6])), tf32r(fmaf(kf, ts[7], wk*facc[7])));
        mr[11] = make_float4(tf32r(fmaf(kf, ts[8], wk*facc[8])), tf32r(fmaf(kf, ts[9], wk*facc[9])),
                             tf32r(fmaf(kf, ts[10], wk*facc[10])), tf32r(fmaf(kf, ts[11], wk*facc[11])));
    }
}

// ================= mlp3: bias-in-row-51, 14 warps, cooperative output scatter =================
#define W1S 192
#define W2S 128
#define HS3 84
#define OW1_3 0
#define OW2_3 10752
#define OB2_3  18944
#define OWRP_3 19072
#define SLAB_3 2688           // 32*84
#define NW3 14
#define NT3 (NW3 * 32)
#define SMEM3_FLOATS (OWRP_3 + NW3 * SLAB_3)   // 226,816 B

__global__ __launch_bounds__(NT3, 1)
void mlp3_kernel(const float* __restrict__ xin,
                 const float* __restrict__ op_w1,  const float* __restrict__ op_b1,
                 const float* __restrict__ op_w2,  const float* __restrict__ op_b2,
                 const float* __restrict__ col_w1, const float* __restrict__ col_b1,
                 const float* __restrict__ col_w2, const float* __restrict__ col_b2,
                 const float* __restrict__ cov_w1, const float* __restrict__ cov_b1,
                 const float* __restrict__ cov_w2, const float* __restrict__ cov_b2,
                 const float* __restrict__ pfv,
                 float* __restrict__ out, int M)
{
    extern __shared__ float S[];
    const int tid = threadIdx.x;
    const int warp = tid >> 5;
    const int lane = tid & 31;

    for (int i = tid; i < 56 * W1S; i += NT3) {
        int row = i / W1S, c = i - row * W1S;
        int sel = c >> 6, cc = c & 63;
        float v = 0.f;
        if (row < 51)
            v = (sel == 0) ? op_w1[row * 64 + cc]
              : (sel == 1) ? col_w1[row * 64 + cc]
                           : cov_w1[row * 64 + cc];
        else if (row == 51)
            v = (sel == 0) ? op_b1[cc] : (sel == 1) ? col_b1[cc] : cov_b1[cc];
        S[OW1_3 + i] = tf32r(v);
    }
    for (int i = tid; i < 64 * W2S; i += NT3) {
        int j = i >> 7, c = i & 127;
        float v = 0.f;
        if (c < 16)       { if (c < 10)      v = op_w2 [j * 10 + c]; }
        else if (c < 48)  { if (c - 16 < 30) v = col_w2[j * 30 + (c - 16)]; }
        else              { if (c - 48 < 70) v = cov_w2[j * 70 + (c - 48)]; }
        S[OW2_3 + i] = tf32r(v);
    }
    if (tid < W2S) {
        float v = 0.f;
        if (tid < 16)      { if (tid < 10)      v = op_b2 [tid]; }
        else if (tid < 48) { if (tid - 16 < 30) v = col_b2[tid - 16]; }
        else               { if (tid - 48 < 70) v = cov_b2[tid - 48]; }
        S[OB2_3 + tid] = v;
    }
    __syncthreads();

    float* Xp = S + OWRP_3 + warp * SLAB_3;
    const int tiles32 = (M + 31) >> 5;

    // per-lane constant scatter offsets
    const int op_col  = lane * 11;                                   // lane<10
    const int col_col = (lane / 3) * 11 + 1 + (lane - 3 * (lane / 3)); // lane<30
    int cov_col[3];
    #pragma unroll
    for (int q = 0; q < 3; q++) {
        int k = q * 32 + lane;
        cov_col[q] = (k < 70) ? ((k / 7) * 11 + 4 + (k - 7 * (k / 7))) : -1;
    }
    const float b2op  = (lane < 10) ? 0.f : 0.f; // placeholder (loaded below after sync)

    for (int t = blockIdx.x * NW3 + warp; t < tiles32; t += gridDim.x * NW3) {
        {
            const float* src = xin + (size_t)t * 32 * 56;
            #pragma unroll
            for (int it = 0; it < 14; it++) {
                int e = lane * 4 + it * 128;
                float4 v = __ldg(reinterpret_cast<const float4*>(src + e));
                int row = e / 56, c = e - row * 56;
                *reinterpret_cast<float4*>(Xp + row * HS3 + c) = v;
            }
        }
        __syncwarp();

        wmma::fragment<wmma::matrix_a, 16, 16, 8, wmma::precision::tf32, wmma::row_major> af[2][7];
        #pragma unroll
        for (int k = 0; k < 7; k++) {
            wmma::load_matrix_sync(af[0][k], Xp + k * 8, HS3);
            wmma::load_matrix_sync(af[1][k], Xp + 16 * HS3 + k * 8, HS3);
        }
        __syncwarp();

        const size_t mlane = (size_t)t * 32 + lane;
        const float pf = (mlane < (size_t)M) ? __ldg(pfv + mlane) : 0.f;
        const int npts = min(32, (int)((size_t)M - (size_t)t * 32));
        float* obase = out + (size_t)t * 32 * 110;

        #pragma unroll 1
        for (int s = 0; s < 3; s++) {
            wmma::fragment<wmma::accumulator, 16, 16, 8, float> c1[2][4];
            #pragma unroll
            for (int n = 0; n < 4; n++) {
                wmma::fill_fragment(c1[0][n], 0.f);
                wmma::fill_fragment(c1[1][n], 0.f);
            }
            #pragma unroll
            for (int k = 0; k < 7; k++) {
                #pragma unroll
                for (int n = 0; n < 4; n++) {
                    wmma::fragment<wmma::matrix_b, 16, 16, 8, wmma::precision::tf32, wmma::row_major> bf;
                    wmma::load_matrix_sync(bf, S + OW1_3 + (k * 8) * W1S + s * 64 + n * 16, W1S);
                    wmma::mma_sync(c1[0][n], af[0][k], bf, c1[0][n]);
                    wmma::mma_sync(c1[1][n], af[1][k], bf, c1[1][n]);
                }
            }
            #pragma unroll
            for (int tt = 0; tt < 2; tt++)
                #pragma unroll
                for (int n = 0; n < 4; n++) {
                    #pragma unroll
                    for (int i = 0; i < c1[tt][n].num_elements; i++)
                        c1[tt][n].x[i] = tf32r(fmaxf(c1[tt][n].x[i], 0.f));
                    wmma::store_matrix_sync(Xp + tt * 16 * HS3 + n * 16, c1[tt][n], HS3, wmma::mem_row_major);
                }
            __syncwarp();

            if (s == 0) {
                wmma::fragment<wmma::accumulator, 16, 16, 8, float> c2[2];
                #pragma unroll
                for (int tt = 0; tt < 2; tt++) wmma::fill_fragment(c2[tt], 0.f);
                #pragma unroll 1
                for (int k = 0; k < 8; k++) {
                    wmma::fragment<wmma::matrix_a, 16, 16, 8, wmma::precision::tf32, wmma::row_major> a0, a1;
                    wmma::load_matrix_sync(a0, Xp + k * 8, HS3);
                    wmma::load_matrix_sync(a1, Xp + 16 * HS3 + k * 8, HS3);
                    wmma::fragment<wmma::matrix_b, 16, 16, 8, wmma::precision::tf32, wmma::row_major> bf;
                    wmma::load_matrix_sync(bf, S + OW2_3 + (k * 8) * W2S + 0, W2S);
                    wmma::mma_sync(c2[0], a0, bf, c2[0]);
                    wmma::mma_sync(c2[1], a1, bf, c2[1]);
                }
                __syncwarp();
                wmma::store_matrix_sync(Xp, c2[0], HS3, wmma::mem_row_major);
                wmma::store_matrix_sync(Xp + 16 * HS3, c2[1], HS3, wmma::mem_row_major);
                __syncwarp();
                // cooperative scatter: lanes 0..9 write point p's op outputs
                float bias = S[OB2_3 + min(lane, 15)];
                #pragma unroll 4
                for (int p = 0; p < npts; p++) {
                    float pfp = __shfl_sync(0xffffffffu, pf, p);
                    if (lane < 10) {
                        float v = Xp[p * HS3 + lane];
                        obase[(size_t)p * 110 + op_col] = tanhf(v + bias) * pfp;
                    }
                }
            } else if (s == 1) {
                wmma::fragment<wmma::accumulator, 16, 16, 8, float> c2[2][2];
                #pragma unroll
                for (int tt = 0; tt < 2; tt++)
                    #pragma unroll
                    for (int n = 0; n < 2; n++) wmma::fill_fragment(c2[tt][n], 0.f);
                #pragma unroll 1
                for (int k = 0; k < 8; k++) {
                    wmma::fragment<wmma::matrix_a, 16, 16, 8, wmma::precision::tf32, wmma::row_major> a0, a1;
                    wmma::load_matrix_sync(a0, Xp + k * 8, HS3);
                    wmma::load_matrix_sync(a1, Xp + 16 * HS3 + k * 8, HS3);
                    #pragma unroll
                    for (int n = 0; n < 2; n++) {
                        wmma::fragment<wmma::matrix_b, 16, 16, 8, wmma::precision::tf32, wmma::row_major> bf;
                        wmma::load_matrix_sync(bf, S + OW2_3 + (k * 8) * W2S + 16 + n * 16, W2S);
                        wmma::mma_sync(c2[0][n], a0, bf, c2[0][n]);
                        wmma::mma_sync(c2[1][n], a1, bf, c2[1][n]);
                    }
                }
                __syncwarp();
                #pragma unroll
                for (int tt = 0; tt < 2; tt++)
                    #pragma unroll
                    for (int n = 0; n < 2; n++)
                        wmma::store_matrix_sync(Xp + tt * 16 * HS3 + n * 16, c2[tt][n], HS3, wmma::mem_row_major);
                __syncwarp();
                float bias = S[OB2_3 + 16 + min(lane, 31)];
                #pragma unroll 4
                for (int p = 0; p < npts; p++) {
                    if (lane < 30) {
                        float v = Xp[p * HS3 + lane];
                        obase[(size_t)p * 110 + col_col] = sigmoidf_(v + bias);
                    }
                }
            } else {
                wmma::fragment<wmma::accumulator, 16, 16, 8, float> c2[2][5];
                #pragma unroll
                for (int tt = 0; tt < 2; tt++)
                    #pragma unroll
                    for (int n = 0; n < 5; n++) wmma::fill_fragment(c2[tt][n], 0.f);
                #pragma unroll 1
                for (int k = 0; k < 8; k++) {
                    wmma::fragment<wmma::matrix_a, 16, 16, 8, wmma::precision::tf32, wmma::row_major> a0, a1;
                    wmma::load_matrix_sync(a0, Xp + k * 8, HS3);
                    wmma::load_matrix_sync(a1, Xp + 16 * HS3 + k * 8, HS3);
                    #pragma unroll
                    for (int n = 0; n < 5; n++) {
                        wmma::fragment<wmma::matrix_b, 16, 16, 8, wmma::precision::tf32, wmma::row_major> bf;
                        wmma::load_matrix_sync(bf, S + OW2_3 + (k * 8) * W2S + 48 + n * 16, W2S);
                        wmma::mma_sync(c2[0][n], a0, bf, c2[0][n]);
                        wmma::mma_sync(c2[1][n], a1, bf, c2[1][n]);
                    }
                }
                __syncwarp();
                #pragma unroll
                for (int tt = 0; tt < 2; tt++)
                    #pragma unroll
                    for (int n = 0; n < 5; n++)
                        wmma::store_matrix_sync(Xp + tt * 16 * HS3 + n * 16, c2[tt][n], HS3, wmma::mem_row_major);
                __syncwarp();
                float bias0 = S[OB2_3 + 48 + lane];
                float bias1 = S[OB2_3 + 48 + 32 + lane];
                float bias2 = (lane < 6) ? S[OB2_3 + 48 + 64 + lane] : 0.f;
                #pragma unroll 2
                for (int p = 0; p < npts; p++) {
                    const float* row = Xp + p * HS3;
                    float* orow = obase + (size_t)p * 110;
                    orow[cov_col[0]] = row[lane] + bias0;
                    orow[cov_col[1]] = row[32 + lane] + bias1;
                    if (lane < 6)
                        orow[cov_col[2]] = row[64 + lane] + bias2;
                }
            }
            __syncwarp();
        }
    }
}

// ================= motion: 32-pt tiles, cooperative scatter =================
#define MHS2 68
#define OW1_M 0
#define OW2_M 3072
#define OB1R_M 6144
#define OB2R_M 7168
#define OWRP_M 7936
#define SLAB_M2 2176
#define SMEMM_FLOATS (OWRP_M + 8 * SLAB_M2)

__global__ __launch_bounds__(256, 2)
void mlp_mot_kernel(const float* __restrict__ xin,
                    const float* __restrict__ w1g, const float* __restrict__ b1g,
                    const float* __restrict__ w2g, const float* __restrict__ b2g,
                    const float* __restrict__ mfv,
                    float* __restrict__ out, int M)
{
    extern __shared__ float S[];
    const int tid = threadIdx.x;
    const int warp = tid >> 5;
    const int lane = tid & 31;

    for (int i = tid; i < 48 * 64; i += 256) S[OW1_M + i] = tf32r(w1g[i]);
    for (int i = tid; i < 64 * 48; i += 256) {
        int j = i / 48, k = i - j * 48;
        S[OW2_M + i] = (k < 37) ? tf32r(w2g[j * 37 + k]) : 0.f;
    }
    if (tid < 64) {
        float acc = b1g[tid];
        #pragma unroll
        for (int t = 0; t < 8; t++) {
            float ang = exp2f((float)t) * 1.5707963267948966f;
            acc = fmaf(sinf(ang), w1g[(48 + t) * 64 + tid], acc);
            acc = fmaf(cosf(ang), w1g[(56 + t) * 64 + tid], acc);
        }
        S[OB1R_M + tid] = acc;
    }
    if (tid < 48) S[OB2R_M + tid] = (tid < 37) ? b2g[tid] : 0.f;
    __syncthreads();
    for (int i = tid; i < 16 * 64; i += 256)
        if (i >= 64) S[OB1R_M + i] = S[OB1R_M + (i & 63)];
    for (int i = tid; i < 16 * 48; i += 256)
        if (i >= 48) S[OB2R_M + i] = S[OB2R_M + (i % 48)];
    __syncthreads();

    float* Xp = S + OWRP_M + warp * SLAB_M2;
    const int tiles32 = (M + 31) >> 5;

    for (int t = blockIdx.x * 8 + warp; t < tiles32; t += gridDim.x * 8) {
        {
            const float* src = xin + (size_t)t * 32 * 48;
            #pragma unroll
            for (int it = 0; it < 12; it++) {
                int e = lane * 4 + it * 128;
                float4 v = __ldg(reinterpret_cast<const float4*>(src + e));
                int row = e / 48, c = e - row * 48;
                *reinterpret_cast<float4*>(Xp + row * MHS2 + c) = v;
            }
        }
        __syncwarp();

        wmma::fragment<wmma::accumulator, 16, 16, 8, float> c1[2][4];
        #pragma unroll
        for (int n = 0; n < 4; n++) {
            wmma::load_matrix_sync(c1[0][n], S + OB1R_M + n * 16, 64, wmma::mem_row_major);
            wmma::load_matrix_sync(c1[1][n], S + OB1R_M + n * 16, 64, wmma::mem_row_major);
        }
        #pragma unroll 1
        for (int k = 0; k < 6; k++) {
            wmma::fragment<wmma::matrix_a, 16, 16, 8, wmma::precision::tf32, wmma::row_major> a0, a1;
            wmma::load_matrix_sync(a0, Xp + k * 8, MHS2);
            wmma::load_matrix_sync(a1, Xp + 16 * MHS2 + k * 8, MHS2);
            #pragma unroll
            for (int n = 0; n < 4; n++) {
                wmma::fragment<wmma::matrix_b, 16, 16, 8, wmma::precision::tf32, wmma::row_major> bf;
                wmma::load_matrix_sync(bf, S + OW1_M + k * 8 * 64 + n * 16, 64);
                wmma::mma_sync(c1[0][n], a0, bf, c1[0][n]);
                wmma::mma_sync(c1[1][n], a1, bf, c1[1][n]);
            }
        }
        #pragma unroll
        for (int tt = 0; tt < 2; tt++)
            #pragma unroll
            for (int n = 0; n < 4; n++) {
                #pragma unroll
                for (int i = 0; i < c1[tt][n].num_elements; i++)
                    c1[tt][n].x[i] = tf32r(fmaxf(c1[tt][n].x[i], 0.f));
                wmma::store_matrix_sync(Xp + tt * 16 * MHS2 + n * 16, c1[tt][n], MHS2, wmma::mem_row_major);
            }
        __syncwarp();

        wmma::fragment<wmma::accumulator, 16, 16, 8, float> c2[2][3];
        #pragma unroll
        for (int n = 0; n < 3; n++) {
            wmma::load_matrix_sync(c2[0][n], S + OB2R_M + n * 16, 48, wmma::mem_row_major);
            wmma::load_matrix_sync(c2[1][n], S + OB2R_M + n * 16, 48, wmma::mem_row_major);
        }
        #pragma unroll 1
        for (int k = 0; k < 8; k++) {
            wmma::fragment<wmma::matrix_a, 16, 16, 8, wmma::precision::tf32, wmma::row_major> a0, a1;
            wmma::load_matrix_sync(a0, Xp + k * 8, MHS2);
            wmma::load_matrix_sync(a1, Xp + 16 * MHS2 + k * 8, MHS2);
            #pragma unroll
            for (int n = 0; n < 3; n++) {
                wmma::fragment<wmma::matrix_b, 16, 16, 8, wmma::precision::tf32, wmma::row_major> bf;
                wmma::load_matrix_sync(bf, S + OW2_M + k * 8 * 48 + n * 16, 48);
                wmma::mma_sync(c2[0][n], a0, bf, c2[0][n]);
                wmma::mma_sync(c2[1][n], a1, bf, c2[1][n]);
            }
        }
        __syncwarp();
        #pragma unroll
        for (int tt = 0; tt < 2; tt++)
            #pragma unroll
            for (int n = 0; n < 3; n++)
                wmma::store_matrix_sync(Xp + tt * 16 * MHS2 + n * 16, c2[tt][n], MHS2, wmma::mem_row_major);
        __syncwarp();

        // cooperative scatter: lanes 0..18 write point p's 37 motion outputs (float2 x18 + 1)
        {
            const size_t mlane = (size_t)t * 32 + lane;
            const float mfs = (mlane < (size_t)M) ? __ldg(mfv + mlane) : 0.f;
            const int npts = min(32, (int)((size_t)M - (size_t)t * 32));
            float* obase = out + (size_t)M * 110 + (size_t)t * 32 * 50;
            #pragma unroll 4
            for (int p = 0; p < npts; p++) {
                float mfp = __shfl_sync(0xffffffffu, mfs, p);
                const float* r = Xp + p * MHS2;
                float* om = obase + (size_t)p * 50;
                if (lane < 18) {
                    float2 v = make_float2(r[2*lane] * mfp, r[2*lane+1] * mfp);
                    *reinterpret_cast<float2*>(om + 2*lane) = v;
                } else if (lane == 18) {
                    om[36] = r[36] * mfp;
                }
            }
        }
        __syncwarp();
    }
}

// ================= launch =================
extern "C" void kernel_launch(void* const* d_in, const int* in_sizes, int n_in,
                              void* d_out, int out_size)
{
    const float* cam     = (const float*)d_in[0];
    const float* anchors = (const float*)d_in[1];
    const float* scales  = (const float*)d_in[2];
    const float* afeat   = (const float*)d_in[3];
    const float* tfeat   = (const float*)d_in[4];
    const float* factors = (const float*)d_in[5];
    const float* op_w1   = (const float*)d_in[6];
    const float* op_b1   = (const float*)d_in[7];
    const float* op_w2   = (const float*)d_in[8];
    const float* op_b2   = (const float*)d_in[9];
    const float* col_w1  = (const float*)d_in[10];
    const float* col_b1  = (const float*)d_in[11];
    const float* col_w2  = (const float*)d_in[12];
    const float* col_b2  = (const float*)d_in[13];
    const float* cov_w1  = (const float*)d_in[14];
    const float* cov_b1  = (const float*)d_in[15];
    const float* cov_w2  = (const float*)d_in[16];
    const float* cov_b2  = (const float*)d_in[17];
    const float* mot_w1  = (const float*)d_in[18];
    const float* mot_b1  = (const float*)d_in[19];
    const float* mot_w2  = (const float*)d_in[20];
    const float* mot_b2  = (const float*)d_in[21];
    const int*   vis     = (const int*)d_in[22];
    const int*   knn     = (const int*)d_in[23];

    int M = in_sizes[22];
    float* out = (float*)d_out;

    float *taf, *tafm, *pf, *mf;
    cudaGetSymbolAddress((void**)&taf,  g_taf);
    cudaGetSymbolAddress((void**)&tafm, g_tafm);
    cudaGetSymbolAddress((void**)&pf,   g_pf);
    cudaGetSymbolAddress((void**)&mf,   g_mf);

    const int GB = (M + 63) / 64;

    const int SMEM3 = SMEM3_FLOATS * 4;
    const int SMEMM = SMEMM_FLOATS * 4;
    cudaFuncSetAttribute(mlp3_kernel,    cudaFuncAttributeMaxDynamicSharedMemorySize, SMEM3);
    cudaFuncSetAttribute(mlp_mot_kernel, cudaFuncAttributeMaxDynamicSharedMemorySize, SMEMM);

    build_kernel<<<GB, 256>>>(cam, anchors, scales, afeat, tfeat, factors, vis, knn, out, M);
    mlp3_kernel<<<148, NT3, SMEM3>>>(
        taf,
        op_w1, op_b1, op_w2, op_b2,
        col_w1, col_b1, col_w2, col_b2,
        cov_w1, cov_b1, cov_w2, cov_b2,
        pf, out, M);
    mlp_mot_kernel<<<296, 256, SMEMM>>>(tafm, mot_w1, mot_b1, mot_w2, mot_b2, mf, out, M);
}